// round 1
// baseline (speedup 1.0000x reference)
#include <cuda_runtime.h>
#include <math.h>
#include <stdint.h>

// Problem dims (fixed)
#define KENT    8
#define BENT    4096
#define MDIM    4096
#define HIN     512
#define HENC    256
#define HCORE   512
#define HCTX    256
#define HSTATE  512
#define NPAIR   (BENT * (KENT - 1))   // 28672
#define HTOT    (HENC + HCTX + HIN)   // 1024

// Scratch in __device__ globals (no allocation allowed)
__device__ float g_X[BENT * HIN];        // elu(inputs@W_in)        8 MB
__device__ float g_S1[BENT * HENC];      // relu(state@W_enc)       4 MB
__device__ float g_core[(size_t)NPAIR * HCORE]; // core_out         56 MB
__device__ float g_ctx[(size_t)NPAIR * HCTX];   // context          28 MB
__device__ float g_att[NPAIR];           // attention               0.11 MB
__device__ float g_E[BENT * HCTX];       // effect sum              4 MB
__device__ float g_T[BENT * HTOT];       // total (concat)          16 MB

template<int ACT>
__device__ __forceinline__ float actf(float v) {
    if (ACT == 1) return fmaxf(v, 0.0f);                  // relu
    if (ACT == 2) return 1.0f / (1.0f + expf(-v));        // sigmoid
    if (ACT == 3) return v > 0.0f ? v : expm1f(v);        // elu (alpha=1)
    return v;
}

// Tiled GEMM: C[M,N] = act(A[M,Kd] @ B[Kd,N] + bias)
// 64x64 tile, BK=16, 256 threads, 4x4 per-thread micro-tile.
// MODE 0: normal A. MODE 1: gathered pair A (A = S1, Kd = 2*HENC,
//   row p -> first 256 k from S1[rcs], last 256 from S1[rfs]).
// Requires: M%64==0, N%64==0, Kd%16==0 (all shapes here satisfy this).
template<int ACT, int MODE>
__global__ void __launch_bounds__(256)
gemm_k(const float* __restrict__ A, const float* __restrict__ B,
       const float* __restrict__ bias, float* __restrict__ C,
       int N, int Kd)
{
    __shared__ float As[16][64];
    __shared__ float Bs[16][64];

    const int tid  = threadIdx.x;
    const int row0 = blockIdx.y * 64;
    const int col0 = blockIdx.x * 64;
    const int ty = tid >> 4;       // 0..15
    const int tx = tid & 15;       // 0..15

    // A-load assignment: thread loads float4 of k for one row
    const int lm = tid >> 2;       // 0..63 (row in tile)
    const int kq = tid & 3;        // 0..3  (k quad)
    // B-load assignment
    const int bk = tid >> 4;       // 0..15 (k row)
    const int bn4 = tid & 15;      // 0..15 (n quad)

    int rcs = 0, rfs = 0;
    if (MODE == 1) {
        int p = row0 + lm;
        int b_ = p / 56;
        int rem = p % 56;
        int i = rem / 7;
        int jj = rem % 7;
        int j = jj + (jj >= i ? 1 : 0);
        rcs = b_ * KENT + j;
        rfs = b_ * KENT + i;
    }

    float acc[4][4];
#pragma unroll
    for (int i = 0; i < 4; i++)
#pragma unroll
        for (int j = 0; j < 4; j++) acc[i][j] = 0.0f;

    for (int k0 = 0; k0 < Kd; k0 += 16) {
        // --- load A tile (transposed into As[k][m]) ---
        float4 av;
        if (MODE == 0) {
            av = *(const float4*)(A + (size_t)(row0 + lm) * Kd + k0 + kq * 4);
        } else {
            int k = k0 + kq * 4;
            if (k < HENC) av = *(const float4*)(A + (size_t)rcs * HENC + k);
            else          av = *(const float4*)(A + (size_t)rfs * HENC + (k - HENC));
        }
        As[kq * 4 + 0][lm] = av.x;
        As[kq * 4 + 1][lm] = av.y;
        As[kq * 4 + 2][lm] = av.z;
        As[kq * 4 + 3][lm] = av.w;

        // --- load B tile ---
        float4 bv = *(const float4*)(B + (size_t)(k0 + bk) * N + col0 + bn4 * 4);
        *(float4*)&Bs[bk][bn4 * 4] = bv;

        __syncthreads();

#pragma unroll
        for (int kk = 0; kk < 16; kk++) {
            float4 a = *(const float4*)&As[kk][ty * 4];
            float4 b = *(const float4*)&Bs[kk][tx * 4];
            acc[0][0] += a.x * b.x; acc[0][1] += a.x * b.y; acc[0][2] += a.x * b.z; acc[0][3] += a.x * b.w;
            acc[1][0] += a.y * b.x; acc[1][1] += a.y * b.y; acc[1][2] += a.y * b.z; acc[1][3] += a.y * b.w;
            acc[2][0] += a.z * b.x; acc[2][1] += a.z * b.y; acc[2][2] += a.z * b.z; acc[2][3] += a.z * b.w;
            acc[3][0] += a.w * b.x; acc[3][1] += a.w * b.y; acc[3][2] += a.w * b.z; acc[3][3] += a.w * b.w;
        }
        __syncthreads();
    }

    // epilogue: bias + activation + store
    float4 bvec = *(const float4*)(bias + col0 + tx * 4);
#pragma unroll
    for (int i = 0; i < 4; i++) {
        int r = row0 + ty * 4 + i;
        float4 v;
        v.x = actf<ACT>(acc[i][0] + bvec.x);
        v.y = actf<ACT>(acc[i][1] + bvec.y);
        v.z = actf<ACT>(acc[i][2] + bvec.z);
        v.w = actf<ACT>(acc[i][3] + bvec.w);
        *(float4*)(C + (size_t)r * N + col0 + tx * 4) = v;
    }
}

// attention: att[p] = sigmoid(core[p,:] . W_att + b_att), one warp per row
__global__ void __launch_bounds__(256)
att_k(const float* __restrict__ core, const float* __restrict__ W_att,
      const float* __restrict__ b_att, float* __restrict__ att)
{
    int warp = (blockIdx.x * blockDim.x + threadIdx.x) >> 5;
    int lane = threadIdx.x & 31;
    if (warp >= NPAIR) return;
    const float* r = core + (size_t)warp * HCORE;
    float s = 0.0f;
#pragma unroll
    for (int k = lane; k < HCORE; k += 32) s += r[k] * W_att[k];
#pragma unroll
    for (int o = 16; o; o >>= 1) s += __shfl_xor_sync(0xFFFFFFFFu, s, o);
    if (lane == 0) att[warp] = 1.0f / (1.0f + expf(-(s + b_att[0])));
}

// E[e,c] = sum_{jj<7} att[e*7+jj] * ctx[e*7+jj, c]
__global__ void __launch_bounds__(256)
esum_k(const float* __restrict__ ctx, const float* __restrict__ att,
       float* __restrict__ E)
{
    int e = blockIdx.x;
    int c = threadIdx.x;   // 0..255
    float s = 0.0f;
#pragma unroll
    for (int jj = 0; jj < 7; jj++) {
        int p = e * 7 + jj;
        s += att[p] * ctx[(size_t)p * HCTX + c];
    }
    E[(size_t)e * HCTX + c] = s;
}

// total row e = [S1(256) | E(256) | X(512)]
__global__ void __launch_bounds__(256)
pack_k(const float* __restrict__ S1, const float* __restrict__ E,
       const float* __restrict__ X, float* __restrict__ T)
{
    int e = blockIdx.x;
    int t = threadIdx.x;
    T[(size_t)e * HTOT + t]           = S1[(size_t)e * HENC + t];
    T[(size_t)e * HTOT + 256 + t]     = E[(size_t)e * HCTX + t];
    T[(size_t)e * HTOT + 512 + t]     = X[(size_t)e * HIN + t];
    T[(size_t)e * HTOT + 768 + t]     = X[(size_t)e * HIN + 256 + t];
}

extern "C" void kernel_launch(void* const* d_in, const int* in_sizes, int n_in,
                              void* d_out, int out_size)
{
    const float* inputs = (const float*)d_in[0];
    const float* state  = (const float*)d_in[1];
    const float* W_in   = (const float*)d_in[2];
    const float* b_in   = (const float*)d_in[3];
    const float* W_enc  = (const float*)d_in[4];
    const float* b_enc  = (const float*)d_in[5];
    const float* W_core = (const float*)d_in[6];
    const float* b_core = (const float*)d_in[7];
    const float* W_ctx  = (const float*)d_in[8];
    const float* b_ctx  = (const float*)d_in[9];
    const float* W_att  = (const float*)d_in[10];
    const float* b_att  = (const float*)d_in[11];
    const float* W_rec  = (const float*)d_in[12];
    const float* b_rec  = (const float*)d_in[13];
    const float* W_out  = (const float*)d_in[14];
    const float* b_out  = (const float*)d_in[15];

    float* out       = (float*)d_out;                       // [4096,4096]
    float* new_state = (float*)d_out + (size_t)BENT * MDIM; // [4096,512]

    float *pX, *pS1, *pCore, *pCtx, *pAtt, *pE, *pT;
    cudaGetSymbolAddress((void**)&pX,    g_X);
    cudaGetSymbolAddress((void**)&pS1,   g_S1);
    cudaGetSymbolAddress((void**)&pCore, g_core);
    cudaGetSymbolAddress((void**)&pCtx,  g_ctx);
    cudaGetSymbolAddress((void**)&pAtt,  g_att);
    cudaGetSymbolAddress((void**)&pE,    g_E);
    cudaGetSymbolAddress((void**)&pT,    g_T);

    // 1) X = elu(inputs @ W_in + b_in)          [4096,512] K=4096
    gemm_k<3,0><<<dim3(HIN/64, BENT/64), 256>>>(inputs, W_in, b_in, pX, HIN, MDIM);
    // 2) S1 = relu(state @ W_enc + b_enc)       [4096,256] K=512
    gemm_k<1,0><<<dim3(HENC/64, BENT/64), 256>>>(state, W_enc, b_enc, pS1, HENC, HSTATE);
    // 3) core = relu([cs|fs] @ W_core + b_core) [28672,512] K=512 (gathered)
    gemm_k<1,1><<<dim3(HCORE/64, NPAIR/64), 256>>>(pS1, W_core, b_core, pCore, HCORE, 2*HENC);
    // 4) ctx = relu(core @ W_ctx + b_ctx)       [28672,256] K=512
    gemm_k<1,0><<<dim3(HCTX/64, NPAIR/64), 256>>>(pCore, W_ctx, b_ctx, pCtx, HCTX, HCORE);
    // 5) att = sigmoid(core @ W_att + b_att)    [28672]
    att_k<<<(NPAIR * 32 + 255) / 256, 256>>>(pCore, W_att, b_att, pAtt);
    // 6) E = sum_j att*ctx                      [4096,256]
    esum_k<<<BENT, 256>>>(pCtx, pAtt, pE);
    // 7) T = [S1 | E | X]                       [4096,1024]
    pack_k<<<BENT, 256>>>(pS1, pE, pX, pT);
    // 8) new_state = sigmoid(T @ W_rec + b_rec) [4096,512] K=1024
    gemm_k<2,0><<<dim3(HSTATE/64, BENT/64), 256>>>(pT, W_rec, b_rec, new_state, HSTATE, HTOT);
    // 9) out = sigmoid(new_state @ W_out + b_out) [4096,4096] K=512
    gemm_k<2,0><<<dim3(MDIM/64, BENT/64), 256>>>(new_state, W_out, b_out, out, MDIM, HSTATE);
}

// round 2
// speedup vs baseline: 2.5767x; 2.5767x over previous
#include <cuda_runtime.h>
#include <math.h>
#include <stdint.h>

// Problem dims (fixed)
#define KENT    8
#define BENT    4096
#define MDIM    4096
#define HIN     512
#define HENC    256
#define HCORE   512
#define HCTX    256
#define HSTATE  512
#define NPAIR   (BENT * (KENT - 1))   // 28672
#define HTOT    (HENC + HCTX + HIN)   // 1024

// Scratch in __device__ globals (no allocation allowed)
__device__ float g_X[BENT * HIN];
__device__ float g_S1[BENT * HENC];
__device__ float g_core[(size_t)NPAIR * HCORE];
__device__ float g_ctx[(size_t)NPAIR * HCTX];
__device__ float g_att[NPAIR];
__device__ float g_E[BENT * HCTX];
__device__ float g_T[BENT * HTOT];

template<int ACT>
__device__ __forceinline__ float actf(float v) {
    if (ACT == 1) return fmaxf(v, 0.0f);                  // relu
    if (ACT == 2) return 1.0f / (1.0f + expf(-v));        // sigmoid
    if (ACT == 3) return v > 0.0f ? v : expm1f(v);        // elu
    return v;
}

__device__ __forceinline__ uint32_t f2tf(float x) {
    uint32_t u;
    asm("cvt.rna.tf32.f32 %0, %1;" : "=r"(u) : "f"(x));
    return u;
}

#define BM 128
#define BN 128
#define BK 16
#define SA 18          // As row stride (padded)
#define SB 132         // Bs row stride (padded)

// tf32 tensor-core GEMM: C[M,N] = act(A[M,K] @ B[K,N] + bias)
// 128x128x16 block tile, 8 warps, each warp 64x32 via m16n8k8 mma.
// MODE 0: normal A. MODE 1: pair-gathered A from S1 (K = 2*HENC).
template<int ACT, int MODE>
__global__ void __launch_bounds__(256)
gemm_tc(const float* __restrict__ A, const float* __restrict__ B,
        const float* __restrict__ bias, float* __restrict__ C,
        int N, int K)
{
    __shared__ uint32_t As[2][BM * SA];
    __shared__ uint32_t Bs[2][BK * SB];

    const int tid  = threadIdx.x;
    const int row0 = blockIdx.y * BM;
    const int col0 = blockIdx.x * BN;

    const int warp = tid >> 5;
    const int lane = tid & 31;
    const int grp  = lane >> 2;      // 0..7
    const int tg   = lane & 3;       // 0..3
    const int wm   = warp >> 2;      // 0..1
    const int wn   = warp & 3;       // 0..3
    const int m_base = wm * 64;
    const int n_base = wn * 32;

    // ---- loader assignments ----
    const int ar = tid >> 2;         // 0..63 : A rows ar and ar+64
    const int ak = (tid & 3) * 4;    // k quad within BK
    const int bk_ = tid >> 4;        // 0..15 : B k-row
    const int bn_ = (tid & 15) * 4;  // B cols bn_ and bn_+64

    // MODE 1: gather offsets (independent of k0, precompute)
    size_t rcs1 = 0, rfs1 = 0, rcs2 = 0, rfs2 = 0;
    if (MODE == 1) {
        int p1 = row0 + ar;
        int b1 = p1 / 56, r1 = p1 % 56;
        int i1 = r1 / 7, jj1 = r1 % 7;
        int j1 = jj1 + (jj1 >= i1 ? 1 : 0);
        rcs1 = (size_t)(b1 * KENT + j1) * HENC;
        rfs1 = (size_t)(b1 * KENT + i1) * HENC;
        int p2 = p1 + 64;
        int b2 = p2 / 56, r2 = p2 % 56;
        int i2 = r2 / 7, jj2 = r2 % 7;
        int j2 = jj2 + (jj2 >= i2 ? 1 : 0);
        rcs2 = (size_t)(b2 * KENT + j2) * HENC;
        rfs2 = (size_t)(b2 * KENT + i2) * HENC;
    }

    float acc[4][4][4];
#pragma unroll
    for (int mt = 0; mt < 4; mt++)
#pragma unroll
        for (int nt = 0; nt < 4; nt++)
#pragma unroll
            for (int c = 0; c < 4; c++) acc[mt][nt][c] = 0.0f;

    float4 a1v, a2v, b1v, b2v;

    // global load of tile at k-offset kg
    auto load_global = [&](int kg) {
        if (MODE == 0) {
            a1v = *(const float4*)(A + (size_t)(row0 + ar) * K + kg + ak);
            a2v = *(const float4*)(A + (size_t)(row0 + ar + 64) * K + kg + ak);
        } else {
            int kk = kg + ak;
            const float* p1 = (kk < HENC) ? (A + rcs1 + kk) : (A + rfs1 + kk - HENC);
            const float* p2 = (kk < HENC) ? (A + rcs2 + kk) : (A + rfs2 + kk - HENC);
            a1v = *(const float4*)p1;
            a2v = *(const float4*)p2;
        }
        const float* bp = B + (size_t)(kg + bk_) * N + col0 + bn_;
        b1v = *(const float4*)bp;
        b2v = *(const float4*)(bp + 64);
    };

    auto store_smem = [&](int buf) {
        uint32_t* a0 = &As[buf][ar * SA + ak];
        a0[0] = f2tf(a1v.x); a0[1] = f2tf(a1v.y); a0[2] = f2tf(a1v.z); a0[3] = f2tf(a1v.w);
        uint32_t* a1 = &As[buf][(ar + 64) * SA + ak];
        a1[0] = f2tf(a2v.x); a1[1] = f2tf(a2v.y); a1[2] = f2tf(a2v.z); a1[3] = f2tf(a2v.w);
        uint32_t* b0 = &Bs[buf][bk_ * SB + bn_];
        b0[0] = f2tf(b1v.x); b0[1] = f2tf(b1v.y); b0[2] = f2tf(b1v.z); b0[3] = f2tf(b1v.w);
        uint32_t* b1 = &Bs[buf][bk_ * SB + bn_ + 64];
        b1[0] = f2tf(b2v.x); b1[1] = f2tf(b2v.y); b1[2] = f2tf(b2v.z); b1[3] = f2tf(b2v.w);
    };

    // prologue
    load_global(0);
    store_smem(0);
    __syncthreads();

    const int nk = K / BK;
    for (int it = 0; it < nk; ++it) {
        const int buf = it & 1;
        if (it + 1 < nk) load_global((it + 1) * BK);

        const uint32_t* Ab = &As[buf][0];
        const uint32_t* Bb = &Bs[buf][0];
#pragma unroll
        for (int ks = 0; ks < 2; ks++) {
            const int kk = ks * 8;
            uint32_t af[4][4], bf[4][2];
#pragma unroll
            for (int mt = 0; mt < 4; mt++) {
                int r = m_base + mt * 16 + grp;
                af[mt][0] = Ab[r * SA + kk + tg];
                af[mt][1] = Ab[(r + 8) * SA + kk + tg];
                af[mt][2] = Ab[r * SA + kk + tg + 4];
                af[mt][3] = Ab[(r + 8) * SA + kk + tg + 4];
            }
#pragma unroll
            for (int nt = 0; nt < 4; nt++) {
                int c = n_base + nt * 8 + grp;
                bf[nt][0] = Bb[(kk + tg) * SB + c];
                bf[nt][1] = Bb[(kk + tg + 4) * SB + c];
            }
#pragma unroll
            for (int mt = 0; mt < 4; mt++) {
#pragma unroll
                for (int nt = 0; nt < 4; nt++) {
                    asm("mma.sync.aligned.m16n8k8.row.col.f32.tf32.tf32.f32 "
                        "{%0,%1,%2,%3}, {%4,%5,%6,%7}, {%8,%9}, {%0,%1,%2,%3};"
                        : "+f"(acc[mt][nt][0]), "+f"(acc[mt][nt][1]),
                          "+f"(acc[mt][nt][2]), "+f"(acc[mt][nt][3])
                        : "r"(af[mt][0]), "r"(af[mt][1]), "r"(af[mt][2]), "r"(af[mt][3]),
                          "r"(bf[nt][0]), "r"(bf[nt][1]));
                }
            }
        }
        if (it + 1 < nk) store_smem(buf ^ 1);
        __syncthreads();
    }

    // epilogue: bias + activation + store (2 f32 per c-pair, contiguous)
#pragma unroll
    for (int nt = 0; nt < 4; nt++) {
        int col = col0 + n_base + nt * 8 + 2 * tg;
        float2 bb = *(const float2*)(bias + col);
#pragma unroll
        for (int mt = 0; mt < 4; mt++) {
            int row = row0 + m_base + mt * 16 + grp;
            float2 v0, v1;
            v0.x = actf<ACT>(acc[mt][nt][0] + bb.x);
            v0.y = actf<ACT>(acc[mt][nt][1] + bb.y);
            v1.x = actf<ACT>(acc[mt][nt][2] + bb.x);
            v1.y = actf<ACT>(acc[mt][nt][3] + bb.y);
            *(float2*)(C + (size_t)row * N + col) = v0;
            *(float2*)(C + (size_t)(row + 8) * N + col) = v1;
        }
    }
}

// attention: att[p] = sigmoid(core[p,:] . W_att + b_att), one warp per row
__global__ void __launch_bounds__(256)
att_k(const float* __restrict__ core, const float* __restrict__ W_att,
      const float* __restrict__ b_att, float* __restrict__ att)
{
    int warp = (blockIdx.x * blockDim.x + threadIdx.x) >> 5;
    int lane = threadIdx.x & 31;
    if (warp >= NPAIR) return;
    const float* r = core + (size_t)warp * HCORE;
    float s = 0.0f;
#pragma unroll
    for (int k = lane; k < HCORE; k += 32) s += r[k] * W_att[k];
#pragma unroll
    for (int o = 16; o; o >>= 1) s += __shfl_xor_sync(0xFFFFFFFFu, s, o);
    if (lane == 0) att[warp] = 1.0f / (1.0f + expf(-(s + b_att[0])));
}

// E[e,c] = sum_{jj<7} att[e*7+jj] * ctx[e*7+jj, c]
__global__ void __launch_bounds__(256)
esum_k(const float* __restrict__ ctx, const float* __restrict__ att,
       float* __restrict__ E)
{
    int e = blockIdx.x;
    int c = threadIdx.x;
    float s = 0.0f;
#pragma unroll
    for (int jj = 0; jj < 7; jj++) {
        int p = e * 7 + jj;
        s += att[p] * ctx[(size_t)p * HCTX + c];
    }
    E[(size_t)e * HCTX + c] = s;
}

// total row e = [S1(256) | E(256) | X(512)]
__global__ void __launch_bounds__(256)
pack_k(const float* __restrict__ S1, const float* __restrict__ E,
       const float* __restrict__ X, float* __restrict__ T)
{
    int e = blockIdx.x;
    int t = threadIdx.x;
    T[(size_t)e * HTOT + t]       = S1[(size_t)e * HENC + t];
    T[(size_t)e * HTOT + 256 + t] = E[(size_t)e * HCTX + t];
    T[(size_t)e * HTOT + 512 + t] = X[(size_t)e * HIN + t];
    T[(size_t)e * HTOT + 768 + t] = X[(size_t)e * HIN + 256 + t];
}

extern "C" void kernel_launch(void* const* d_in, const int* in_sizes, int n_in,
                              void* d_out, int out_size)
{
    const float* inputs = (const float*)d_in[0];
    const float* state  = (const float*)d_in[1];
    const float* W_in   = (const float*)d_in[2];
    const float* b_in   = (const float*)d_in[3];
    const float* W_enc  = (const float*)d_in[4];
    const float* b_enc  = (const float*)d_in[5];
    const float* W_core = (const float*)d_in[6];
    const float* b_core = (const float*)d_in[7];
    const float* W_ctx  = (const float*)d_in[8];
    const float* b_ctx  = (const float*)d_in[9];
    const float* W_att  = (const float*)d_in[10];
    const float* b_att  = (const float*)d_in[11];
    const float* W_rec  = (const float*)d_in[12];
    const float* b_rec  = (const float*)d_in[13];
    const float* W_out  = (const float*)d_in[14];
    const float* b_out  = (const float*)d_in[15];

    float* out       = (float*)d_out;
    float* new_state = (float*)d_out + (size_t)BENT * MDIM;

    float *pX, *pS1, *pCore, *pCtx, *pAtt, *pE, *pT;
    cudaGetSymbolAddress((void**)&pX,    g_X);
    cudaGetSymbolAddress((void**)&pS1,   g_S1);
    cudaGetSymbolAddress((void**)&pCore, g_core);
    cudaGetSymbolAddress((void**)&pCtx,  g_ctx);
    cudaGetSymbolAddress((void**)&pAtt,  g_att);
    cudaGetSymbolAddress((void**)&pE,    g_E);
    cudaGetSymbolAddress((void**)&pT,    g_T);

    // 1) X = elu(inputs @ W_in + b_in)            [4096,512]  K=4096
    gemm_tc<3,0><<<dim3(HIN/BN, BENT/BM), 256>>>(inputs, W_in, b_in, pX, HIN, MDIM);
    // 2) S1 = relu(state @ W_enc + b_enc)         [4096,256]  K=512
    gemm_tc<1,0><<<dim3(HENC/BN, BENT/BM), 256>>>(state, W_enc, b_enc, pS1, HENC, HSTATE);
    // 3) core = relu([cs|fs] @ W_core + b_core)   [28672,512] K=512 gathered
    gemm_tc<1,1><<<dim3(HCORE/BN, NPAIR/BM), 256>>>(pS1, W_core, b_core, pCore, HCORE, 2*HENC);
    // 4) ctx = relu(core @ W_ctx + b_ctx)         [28672,256] K=512
    gemm_tc<1,0><<<dim3(HCTX/BN, NPAIR/BM), 256>>>(pCore, W_ctx, b_ctx, pCtx, HCTX, HCORE);
    // 5) att = sigmoid(core @ W_att + b_att)      [28672]
    att_k<<<(NPAIR * 32 + 255) / 256, 256>>>(pCore, W_att, b_att, pAtt);
    // 6) E = sum_j att*ctx                        [4096,256]
    esum_k<<<BENT, 256>>>(pCtx, pAtt, pE);
    // 7) T = [S1 | E | X]                         [4096,1024]
    pack_k<<<BENT, 256>>>(pS1, pE, pX, pT);
    // 8) new_state = sigmoid(T @ W_rec + b_rec)   [4096,512]  K=1024
    gemm_tc<2,0><<<dim3(HSTATE/BN, BENT/BM), 256>>>(pT, W_rec, b_rec, new_state, HSTATE, HTOT);
    // 9) out = sigmoid(new_state @ W_out + b_out) [4096,4096] K=512
    gemm_tc<2,0><<<dim3(MDIM/BN, BENT/BM), 256>>>(new_state, W_out, b_out, out, MDIM, HSTATE);
}

// round 4
// speedup vs baseline: 4.2167x; 1.6365x over previous
#include <cuda_runtime.h>
#include <cuda_fp16.h>
#include <math.h>
#include <stdint.h>

// Problem dims (fixed)
#define KENT    8
#define BENT    4096
#define MDIM    4096
#define HIN     512
#define HENC    256
#define HCORE   512
#define HCTX    256
#define HSTATE  512
#define NPAIR   (BENT * (KENT - 1))   // 28672
#define HTOT    (HENC + HCTX + HIN)   // 1024

// Scratch in __device__ globals (no allocation allowed)
__device__ float g_X[BENT * HIN];
__device__ float g_S1[BENT * HENC];
__device__ float g_core[(size_t)NPAIR * HCORE];
__device__ float g_ctx[(size_t)NPAIR * HCTX];
__device__ float g_att[NPAIR];
__device__ float g_E[BENT * HCTX];
__device__ float g_T[BENT * HTOT];

template<int ACT>
__device__ __forceinline__ float actf(float v) {
    if (ACT == 1) return fmaxf(v, 0.0f);                  // relu
    if (ACT == 2) return 1.0f / (1.0f + expf(-v));        // sigmoid
    if (ACT == 3) return v > 0.0f ? v : expm1f(v);        // elu
    return v;
}

__device__ __forceinline__ uint32_t pkh(float a, float b) {
    __half2 h = __floats2half2_rn(a, b);
    return *reinterpret_cast<uint32_t*>(&h);
}

// SMEM layout constants (bytes)
#define ASTR 80      // A row stride: 32 fp16 = 64B data + 16B pad (ldmatrix conflict-free)
#define BSTR 272     // B row stride: 128 fp16 = 256B data + 16B pad
#define ABUF (128 * ASTR)   // 10240
#define BBUF (32 * BSTR)    // 8704

// fp16 tensor-core GEMM: C[M,N] = act(A[M,K] @ B[K,N] + bias)
// 128x128 CTA tile, BK=32, 8 warps (2x4), warp tile 64x32 via m16n8k16.
// A fragments via ldmatrix.x4, B via ldmatrix.x4.trans (B staged [k][n] row-major).
// MODE 0: normal A. MODE 1: pair-gathered A from S1 (K = 2*HENC).
template<int ACT, int MODE>
__global__ void __launch_bounds__(256)
hgemm(const float* __restrict__ A, const float* __restrict__ B,
      const float* __restrict__ bias, float* __restrict__ C,
      int N, int K)
{
    __shared__ char sm[2 * ABUF + 2 * BBUF];   // 37888 B
    const uint32_t smb = (uint32_t)__cvta_generic_to_shared(sm);
    const uint32_t asb0 = smb;
    const uint32_t bsb0 = smb + 2 * ABUF;

    const int tid  = threadIdx.x;
    const int warp = tid >> 5;
    const int lane = tid & 31;
    const int row0 = blockIdx.y * 128;
    const int col0 = blockIdx.x * 128;

    const int wm = warp >> 2;          // 0..1
    const int wn = warp & 3;           // 0..3
    const int m_base = wm * 64;
    const int n_base = wn * 32;
    const int grp = lane >> 2;         // 0..7
    const int tg  = lane & 3;          // 0..3

    // ---- ldmatrix per-lane offsets ----
    // A (row-major m16k16): lanes 0-7 rows 0-7 k0 | 8-15 rows 8-15 k0 |
    //                       16-23 rows 0-7 k8 | 24-31 rows 8-15 k8
    const int a_row = (lane & 7) + ((lane >> 3) & 1) * 8;
    const int a_kh  = (lane >> 4) * 8;
    const uint32_t aLane = (uint32_t)((m_base + a_row) * ASTR + a_kh * 2);
    // B (staged [k][n], trans): lanes 0-7 k0-7 | 8-15 k8-15 at col n |
    //                          16-23 k0-7 | 24-31 k8-15 at col n+8
    const int b_k  = (lane & 7) + ((lane >> 3) & 1) * 8;
    const int b_nh = (lane >> 4) * 8;
    const uint32_t bLane = (uint32_t)(b_k * BSTR + (n_base + b_nh) * 2);

    // ---- loader assignments ----
    // A: 128 rows x 32 k fp32 -> 4 float4/thread. r = tid>>3 + 32i, k = (tid&7)*4
    const int ar0 = tid >> 3;          // 0..31
    const int akq = tid & 7;           // 0..7
    uint32_t aoff[4];                  // smem store offsets
    uint32_t agbl[4], ag2[4];          // global offsets (elements)
#pragma unroll
    for (int i = 0; i < 4; i++) {
        int r = ar0 + 32 * i;
        aoff[i] = (uint32_t)(r * ASTR + akq * 8);
        if (MODE == 0) {
            agbl[i] = (uint32_t)(row0 + r) * (uint32_t)K + akq * 4;
            ag2[i] = 0;
        } else {
            int p = row0 + r;
            int b_ = p / 56, rem = p % 56;
            int ii = rem / 7, jj = rem % 7;
            int j = jj + (jj >= ii ? 1 : 0);
            agbl[i] = (uint32_t)(b_ * KENT + j) * HENC;    // cs (k < 256)
            ag2[i]  = (uint32_t)(b_ * KENT + ii) * HENC;   // fs (k >= 256)
        }
    }
    // B: 32 k-rows x 128 cols -> 4 float4/thread. kr = tid>>5 + 8i, nc = (tid&31)*4
    const int bkr0 = tid >> 5;         // 0..7
    const int bnc  = (tid & 31) * 4;
    uint32_t boff[4];
#pragma unroll
    for (int i = 0; i < 4; i++)
        boff[i] = (uint32_t)((bkr0 + 8 * i) * BSTR + bnc * 2);

    float acc[4][4][4];
#pragma unroll
    for (int mt = 0; mt < 4; mt++)
#pragma unroll
        for (int nt = 0; nt < 4; nt++)
#pragma unroll
            for (int c = 0; c < 4; c++) acc[mt][nt][c] = 0.0f;

    uint2 avh[4], bvh[4];   // staged fp16-packed tiles

    auto load_global = [&](int kg) {
#pragma unroll
        for (int i = 0; i < 4; i++) {
            float4 v;
            if (MODE == 0) {
                v = *(const float4*)(A + (size_t)agbl[i] + kg);
            } else {
                int kk = kg + akq * 4;
                const float* p = (kk < HENC) ? (A + agbl[i] + kk)
                                             : (A + ag2[i] + (kk - HENC));
                v = *(const float4*)p;
            }
            avh[i].x = pkh(v.x, v.y);
            avh[i].y = pkh(v.z, v.w);
        }
#pragma unroll
        for (int i = 0; i < 4; i++) {
            const float* p = B + (size_t)(kg + bkr0 + 8 * i) * N + col0 + bnc;
            float4 v = *(const float4*)p;
            bvh[i].x = pkh(v.x, v.y);
            bvh[i].y = pkh(v.z, v.w);
        }
    };

    auto store_smem = [&](int buf) {
        uint32_t ab = asb0 + (uint32_t)buf * ABUF;
        uint32_t bb = bsb0 + (uint32_t)buf * BBUF;
#pragma unroll
        for (int i = 0; i < 4; i++)
            asm volatile("st.shared.v2.b32 [%0], {%1,%2};"
                         :: "r"(ab + aoff[i]), "r"(avh[i].x), "r"(avh[i].y) : "memory");
#pragma unroll
        for (int i = 0; i < 4; i++)
            asm volatile("st.shared.v2.b32 [%0], {%1,%2};"
                         :: "r"(bb + boff[i]), "r"(bvh[i].x), "r"(bvh[i].y) : "memory");
    };

    load_global(0);
    store_smem(0);
    __syncthreads();

    const int nk = K >> 5;
    for (int it = 0; it < nk; ++it) {
        const int buf = it & 1;
        if (it + 1 < nk) load_global((it + 1) << 5);

        const uint32_t ab = asb0 + (uint32_t)buf * ABUF + aLane;
        const uint32_t bb = bsb0 + (uint32_t)buf * BBUF + bLane;
#pragma unroll
        for (int ks = 0; ks < 2; ks++) {
            uint32_t af[4][4];
#pragma unroll
            for (int mt = 0; mt < 4; mt++) {
                uint32_t addr = ab + mt * (16 * ASTR) + ks * 32;
                asm volatile("ldmatrix.sync.aligned.m8n8.x4.shared.b16 {%0,%1,%2,%3}, [%4];"
                             : "=r"(af[mt][0]), "=r"(af[mt][1]),
                               "=r"(af[mt][2]), "=r"(af[mt][3])
                             : "r"(addr));
            }
            uint32_t bf[4][2];
#pragma unroll
            for (int nt2 = 0; nt2 < 2; nt2++) {
                uint32_t addr = bb + nt2 * 32 + ks * (16 * BSTR);
                asm volatile("ldmatrix.sync.aligned.m8n8.x4.trans.shared.b16 {%0,%1,%2,%3}, [%4];"
                             : "=r"(bf[nt2*2][0]), "=r"(bf[nt2*2][1]),
                               "=r"(bf[nt2*2+1][0]), "=r"(bf[nt2*2+1][1])
                             : "r"(addr));
            }
#pragma unroll
            for (int mt = 0; mt < 4; mt++) {
#pragma unroll
                for (int nt = 0; nt < 4; nt++) {
                    asm("mma.sync.aligned.m16n8k16.row.col.f32.f16.f16.f32 "
                        "{%0,%1,%2,%3}, {%4,%5,%6,%7}, {%8,%9}, {%0,%1,%2,%3};"
                        : "+f"(acc[mt][nt][0]), "+f"(acc[mt][nt][1]),
                          "+f"(acc[mt][nt][2]), "+f"(acc[mt][nt][3])
                        : "r"(af[mt][0]), "r"(af[mt][1]), "r"(af[mt][2]), "r"(af[mt][3]),
                          "r"(bf[nt][0]), "r"(bf[nt][1]));
                }
            }
        }
        if (it + 1 < nk) store_smem(buf ^ 1);
        __syncthreads();
    }

    // epilogue: bias + activation + float2 stores
#pragma unroll
    for (int nt = 0; nt < 4; nt++) {
        int col = col0 + n_base + nt * 8 + 2 * tg;
        float2 bb = *(const float2*)(bias + col);
#pragma unroll
        for (int mt = 0; mt < 4; mt++) {
            int row = row0 + m_base + mt * 16 + grp;
            float2 v0, v1;
            v0.x = actf<ACT>(acc[mt][nt][0] + bb.x);
            v0.y = actf<ACT>(acc[mt][nt][1] + bb.y);
            v1.x = actf<ACT>(acc[mt][nt][2] + bb.x);
            v1.y = actf<ACT>(acc[mt][nt][3] + bb.y);
            *(float2*)(C + (size_t)row * N + col) = v0;
            *(float2*)(C + (size_t)(row + 8) * N + col) = v1;
        }
    }
}

// ---------- glue kernels ----------
__global__ void __launch_bounds__(256)
att_k(const float* __restrict__ core, const float* __restrict__ W_att,
      const float* __restrict__ b_att, float* __restrict__ att)
{
    int w = (blockIdx.x * blockDim.x + threadIdx.x) >> 5;
    int l = threadIdx.x & 31;
    if (w >= NPAIR) return;
    const float* r = core + (size_t)w * HCORE;
    float s = 0.0f;
#pragma unroll
    for (int k = l; k < HCORE; k += 32) s += r[k] * W_att[k];
#pragma unroll
    for (int o = 16; o; o >>= 1) s += __shfl_xor_sync(0xFFFFFFFFu, s, o);
    if (l == 0) att[w] = 1.0f / (1.0f + expf(-(s + b_att[0])));
}

__global__ void __launch_bounds__(256)
esum_k(const float* __restrict__ ctx, const float* __restrict__ att,
       float* __restrict__ E)
{
    int e = blockIdx.x;
    int c = threadIdx.x;
    float s = 0.0f;
#pragma unroll
    for (int jj = 0; jj < 7; jj++) {
        int p = e * 7 + jj;
        s += att[p] * ctx[(size_t)p * HCTX + c];
    }
    E[(size_t)e * HCTX + c] = s;
}

__global__ void __launch_bounds__(256)
pack_k(const float* __restrict__ S1, const float* __restrict__ E,
       const float* __restrict__ X, float* __restrict__ T)
{
    int e = blockIdx.x;
    int t = threadIdx.x;
    T[(size_t)e * HTOT + t]       = S1[(size_t)e * HENC + t];
    T[(size_t)e * HTOT + 256 + t] = E[(size_t)e * HCTX + t];
    T[(size_t)e * HTOT + 512 + t] = X[(size_t)e * HIN + t];
    T[(size_t)e * HTOT + 768 + t] = X[(size_t)e * HIN + 256 + t];
}

extern "C" void kernel_launch(void* const* d_in, const int* in_sizes, int n_in,
                              void* d_out, int out_size)
{
    const float* inputs = (const float*)d_in[0];
    const float* state  = (const float*)d_in[1];
    const float* W_in   = (const float*)d_in[2];
    const float* b_in   = (const float*)d_in[3];
    const float* W_enc  = (const float*)d_in[4];
    const float* b_enc  = (const float*)d_in[5];
    const float* W_core = (const float*)d_in[6];
    const float* b_core = (const float*)d_in[7];
    const float* W_ctx  = (const float*)d_in[8];
    const float* b_ctx  = (const float*)d_in[9];
    const float* W_att  = (const float*)d_in[10];
    const float* b_att  = (const float*)d_in[11];
    const float* W_rec  = (const float*)d_in[12];
    const float* b_rec  = (const float*)d_in[13];
    const float* W_out  = (const float*)d_in[14];
    const float* b_out  = (const float*)d_in[15];

    float* out       = (float*)d_out;
    float* new_state = (float*)d_out + (size_t)BENT * MDIM;

    float *pX, *pS1, *pCore, *pCtx, *pAtt, *pE, *pT;
    cudaGetSymbolAddress((void**)&pX,    g_X);
    cudaGetSymbolAddress((void**)&pS1,   g_S1);
    cudaGetSymbolAddress((void**)&pCore, g_core);
    cudaGetSymbolAddress((void**)&pCtx,  g_ctx);
    cudaGetSymbolAddress((void**)&pAtt,  g_att);
    cudaGetSymbolAddress((void**)&pE,    g_E);
    cudaGetSymbolAddress((void**)&pT,    g_T);

    // 1) X = elu(inputs @ W_in + b_in)            [4096,512]  K=4096
    hgemm<3,0><<<dim3(HIN/128, BENT/128), 256>>>(inputs, W_in, b_in, pX, HIN, MDIM);
    // 2) S1 = relu(state @ W_enc + b_enc)         [4096,256]  K=512
    hgemm<1,0><<<dim3(HENC/128, BENT/128), 256>>>(state, W_enc, b_enc, pS1, HENC, HSTATE);
    // 3) core = relu([cs|fs] @ W_core + b_core)   [28672,512] K=512 gathered
    hgemm<1,1><<<dim3(HCORE/128, NPAIR/128), 256>>>(pS1, W_core, b_core, pCore, HCORE, 2*HENC);
    // 4) ctx = relu(core @ W_ctx + b_ctx)         [28672,256] K=512
    hgemm<1,0><<<dim3(HCTX/128, NPAIR/128), 256>>>(pCore, W_ctx, b_ctx, pCtx, HCTX, HCORE);
    // 5) att = sigmoid(core @ W_att + b_att)      [28672]
    att_k<<<(NPAIR * 32 + 255) / 256, 256>>>(pCore, W_att, b_att, pAtt);
    // 6) E = sum_j att*ctx                        [4096,256]
    esum_k<<<BENT, 256>>>(pCtx, pAtt, pE);
    // 7) T = [S1 | E | X]                         [4096,1024]
    pack_k<<<BENT, 256>>>(pS1, pE, pX, pT);
    // 8) new_state = sigmoid(T @ W_rec + b_rec)   [4096,512]  K=1024
    hgemm<2,0><<<dim3(HSTATE/128, BENT/128), 256>>>(pT, W_rec, b_rec, new_state, HSTATE, HTOT);
    // 9) out = sigmoid(new_state @ W_out + b_out) [4096,4096] K=512
    hgemm<2,0><<<dim3(MDIM/128, BENT/128), 256>>>(new_state, W_out, b_out, out, MDIM, HSTATE);
}

// round 5
// speedup vs baseline: 5.9430x; 1.4094x over previous
#include <cuda_runtime.h>
#include <cuda_fp16.h>
#include <math.h>
#include <stdint.h>

// Problem dims (fixed)
#define KENT    8
#define BENT    4096
#define MDIM    4096
#define HIN     512
#define HENC    256
#define HCORE   512
#define HCTX    256
#define HSTATE  512
#define NPAIR   (BENT * (KENT - 1))   // 28672
#define HTOT    (HENC + HCTX + HIN)   // 1024

// ---- fp16 scratch (no allocation allowed) ----
__device__ __half g_inh[(size_t)BENT * MDIM];      // inputs fp16      32 MB
__device__ __half g_sth[BENT * HSTATE];            // state fp16
__device__ __half g_Winh[MDIM * HIN];
__device__ __half g_Wench[HSTATE * HENC];
__device__ __half g_Wcoreh[2 * HENC * HCORE];
__device__ __half g_Wctxh[HCORE * HCTX];
__device__ __half g_Wrech[HTOT * HSTATE];
__device__ __half g_Wouth[HSTATE * MDIM];
__device__ __half g_Xh[BENT * HIN];
__device__ __half g_S1h[BENT * HENC];
__device__ __half g_coreh[(size_t)NPAIR * HCORE]; // 28 MB
__device__ __half g_ctxh[(size_t)NPAIR * HCTX];   // 14 MB
__device__ float  g_att[NPAIR];
__device__ __half g_Eh[BENT * HCTX];
__device__ __half g_Th[BENT * HTOT];
__device__ __half g_NSh[BENT * HSTATE];

template<int ACT>
__device__ __forceinline__ float actf(float v) {
    if (ACT == 1) return fmaxf(v, 0.0f);                  // relu
    if (ACT == 2) return 1.0f / (1.0f + expf(-v));        // sigmoid
    if (ACT == 3) return v > 0.0f ? v : expm1f(v);        // elu
    return v;
}

// fp32 -> fp16 bulk convert, 8 elems/thread
__global__ void __launch_bounds__(256)
cvt_k(const float* __restrict__ s, __half* __restrict__ d, int n)
{
    int i = (blockIdx.x * blockDim.x + threadIdx.x) * 8;
    if (i >= n) return;
    float4 a = *(const float4*)(s + i);
    float4 b = *(const float4*)(s + i + 4);
    __half2 h0 = __floats2half2_rn(a.x, a.y);
    __half2 h1 = __floats2half2_rn(a.z, a.w);
    __half2 h2 = __floats2half2_rn(b.x, b.y);
    __half2 h3 = __floats2half2_rn(b.z, b.w);
    uint4 o;
    o.x = *(uint32_t*)&h0; o.y = *(uint32_t*)&h1;
    o.z = *(uint32_t*)&h2; o.w = *(uint32_t*)&h3;
    *(uint4*)(d + i) = o;
}

// ---- SMEM layout (bytes) ----
#define STAGES 4
#define ASTR 80                       // 32 fp16 + 16B pad, 16B-aligned stride
#define BSTR 272                      // 128 fp16 + 16B pad
#define ABUF (128 * ASTR)             // 10240
#define BBUF (32 * BSTR)              // 8704
#define STGB (ABUF + BBUF)            // 18944
#define SMEM_TOT (STAGES * STGB)      // 75776

__device__ __forceinline__ void cp16(uint32_t dst, const void* src) {
    asm volatile("cp.async.cg.shared.global [%0], [%1], 16;" :: "r"(dst), "l"(src));
}

// fp16 tensor-core GEMM, cp.async 4-stage pipeline.
// C = act(A[M,K] @ B[K,N] + bias); A,B fp16 row-major; acc fp32.
// 128x128 CTA tile, BK=32, 8 warps (2x4), warp tile 64x32 (m16n8k16).
// MODE 0: normal A. MODE 1: pair-gathered A from S1h (K = 2*HENC).
// WOUT 0: fp16 C only. 1: fp32 C only. 2: both.
template<int ACT, int MODE, int WOUT>
__global__ void __launch_bounds__(256)
hgemm(const __half* __restrict__ A, const __half* __restrict__ B,
      const float* __restrict__ bias, __half* __restrict__ Ch,
      float* __restrict__ Cf, int N, int K)
{
    extern __shared__ char sm[];
    const uint32_t smb = (uint32_t)__cvta_generic_to_shared(sm);

    const int tid  = threadIdx.x;
    const int warp = tid >> 5;
    const int lane = tid & 31;
    const int row0 = blockIdx.y * 128;
    const int col0 = blockIdx.x * 128;

    const int wm = warp >> 2, wn = warp & 3;
    const int m_base = wm * 64, n_base = wn * 32;
    const int grp = lane >> 2, tg = lane & 3;

    // ldmatrix lane offsets (same proven layout as before)
    const int a_row = (lane & 7) + ((lane >> 3) & 1) * 8;
    const int a_kh  = (lane >> 4) * 8;
    const uint32_t aLane = (uint32_t)((m_base + a_row) * ASTR + a_kh * 2);
    const int b_k  = (lane & 7) + ((lane >> 3) & 1) * 8;
    const int b_nh = (lane >> 4) * 8;
    const uint32_t bLane = (uint32_t)(b_k * BSTR + (n_base + b_nh) * 2);

    // ---- cp.async loader assignments ----
    // A tile: 128 rows x 32 fp16 (64B/row). thread -> row tid>>1, 32B at (tid&1)*32
    const int arow = tid >> 1;
    const int ak16 = (tid & 1) * 16;          // fp16 element offset
    const uint32_t aoff = (uint32_t)(arow * ASTR + ak16 * 2);
    size_t rcs = 0, rfs = 0;
    const __half* aBase = nullptr;
    if (MODE == 0) {
        aBase = A + (size_t)(row0 + arow) * K + ak16;
    } else {
        int p = row0 + arow;
        int b_ = p / 56, rem = p % 56;
        int ii = rem / 7, jj = rem % 7;
        int j = jj + (jj >= ii ? 1 : 0);
        rcs = (size_t)(b_ * KENT + j) * HENC;    // k < 256
        rfs = (size_t)(b_ * KENT + ii) * HENC;   // k >= 256
    }
    // B tile: 32 rows x 128 fp16 (256B/row). thread -> row tid>>3, 32B at (tid&7)*32
    const int brow = tid >> 3;
    const int bo16 = (tid & 7) * 16;
    const uint32_t boff = (uint32_t)(brow * BSTR + bo16 * 2);
    const __half* bBase = B + (size_t)brow * N + col0 + bo16;

    auto issue_stage = [&](int s, int kg) {
        uint32_t ab = smb + (uint32_t)s * STGB;
        uint32_t bb = ab + ABUF;
        const __half* asrc;
        if (MODE == 0) {
            asrc = aBase + kg;
        } else {
            int kk = kg + ak16;
            asrc = (kk < HENC) ? (A + rcs + kk) : (A + rfs + (kk - HENC));
        }
        cp16(ab + aoff, asrc);
        cp16(ab + aoff + 16, asrc + 8);
        const __half* bsrc = bBase + (size_t)kg * N;
        cp16(bb + boff, bsrc);
        cp16(bb + boff + 16, bsrc + 8);
    };

    float acc[4][4][4];
#pragma unroll
    for (int mt = 0; mt < 4; mt++)
#pragma unroll
        for (int nt = 0; nt < 4; nt++)
#pragma unroll
            for (int c = 0; c < 4; c++) acc[mt][nt][c] = 0.0f;

    const int nk = K >> 5;

    // prologue: stages 0..2
#pragma unroll
    for (int s = 0; s < STAGES - 1; s++) {
        if (s < nk) issue_stage(s, s << 5);
        asm volatile("cp.async.commit_group;" ::: "memory");
    }

    for (int it = 0; it < nk; ++it) {
        asm volatile("cp.async.wait_group %0;" :: "n"(STAGES - 2) : "memory");
        __syncthreads();
        const int nxt = it + STAGES - 1;
        if (nxt < nk) issue_stage(nxt & (STAGES - 1), nxt << 5);
        asm volatile("cp.async.commit_group;" ::: "memory");

        const uint32_t ab = smb + (uint32_t)(it & (STAGES - 1)) * STGB + aLane;
        const uint32_t bb = smb + (uint32_t)(it & (STAGES - 1)) * STGB + ABUF + bLane;
#pragma unroll
        for (int ks = 0; ks < 2; ks++) {
            uint32_t af[4][4];
#pragma unroll
            for (int mt = 0; mt < 4; mt++) {
                uint32_t addr = ab + mt * (16 * ASTR) + ks * 32;
                asm volatile("ldmatrix.sync.aligned.m8n8.x4.shared.b16 {%0,%1,%2,%3}, [%4];"
                             : "=r"(af[mt][0]), "=r"(af[mt][1]),
                               "=r"(af[mt][2]), "=r"(af[mt][3])
                             : "r"(addr));
            }
            uint32_t bf[4][2];
#pragma unroll
            for (int nt2 = 0; nt2 < 2; nt2++) {
                uint32_t addr = bb + nt2 * 32 + ks * (16 * BSTR);
                asm volatile("ldmatrix.sync.aligned.m8n8.x4.trans.shared.b16 {%0,%1,%2,%3}, [%4];"
                             : "=r"(bf[nt2*2][0]), "=r"(bf[nt2*2][1]),
                               "=r"(bf[nt2*2+1][0]), "=r"(bf[nt2*2+1][1])
                             : "r"(addr));
            }
#pragma unroll
            for (int mt = 0; mt < 4; mt++) {
#pragma unroll
                for (int nt = 0; nt < 4; nt++) {
                    asm("mma.sync.aligned.m16n8k16.row.col.f32.f16.f16.f32 "
                        "{%0,%1,%2,%3}, {%4,%5,%6,%7}, {%8,%9}, {%0,%1,%2,%3};"
                        : "+f"(acc[mt][nt][0]), "+f"(acc[mt][nt][1]),
                          "+f"(acc[mt][nt][2]), "+f"(acc[mt][nt][3])
                        : "r"(af[mt][0]), "r"(af[mt][1]), "r"(af[mt][2]), "r"(af[mt][3]),
                          "r"(bf[nt][0]), "r"(bf[nt][1]));
                }
            }
        }
    }

    // epilogue
#pragma unroll
    for (int nt = 0; nt < 4; nt++) {
        int col = col0 + n_base + nt * 8 + 2 * tg;
        float2 bb2 = *(const float2*)(bias + col);
#pragma unroll
        for (int mt = 0; mt < 4; mt++) {
            int row = row0 + m_base + mt * 16 + grp;
            float v00 = actf<ACT>(acc[mt][nt][0] + bb2.x);
            float v01 = actf<ACT>(acc[mt][nt][1] + bb2.y);
            float v10 = actf<ACT>(acc[mt][nt][2] + bb2.x);
            float v11 = actf<ACT>(acc[mt][nt][3] + bb2.y);
            if (WOUT != 1) {
                __half2 h0 = __floats2half2_rn(v00, v01);
                __half2 h1 = __floats2half2_rn(v10, v11);
                *(__half2*)(Ch + (size_t)row * N + col) = h0;
                *(__half2*)(Ch + (size_t)(row + 8) * N + col) = h1;
            }
            if (WOUT != 0) {
                float2 f0 = {v00, v01}, f1 = {v10, v11};
                *(float2*)(Cf + (size_t)row * N + col) = f0;
                *(float2*)(Cf + (size_t)(row + 8) * N + col) = f1;
            }
        }
    }
}

// ---------- glue kernels (fp16 I/O) ----------
__global__ void __launch_bounds__(256)
att_k(const __half* __restrict__ core, const float* __restrict__ W_att,
      const float* __restrict__ b_att, float* __restrict__ att)
{
    int w = (blockIdx.x * blockDim.x + threadIdx.x) >> 5;
    int l = threadIdx.x & 31;
    if (w >= NPAIR) return;
    const __half* r = core + (size_t)w * HCORE;
    float s = 0.0f;
#pragma unroll
    for (int k = l; k < HCORE; k += 32) s += __half2float(r[k]) * W_att[k];
#pragma unroll
    for (int o = 16; o; o >>= 1) s += __shfl_xor_sync(0xFFFFFFFFu, s, o);
    if (l == 0) att[w] = 1.0f / (1.0f + expf(-(s + b_att[0])));
}

__global__ void __launch_bounds__(256)
esum_k(const __half* __restrict__ ctx, const float* __restrict__ att,
       __half* __restrict__ E)
{
    int e = blockIdx.x;
    int c = threadIdx.x;
    float s = 0.0f;
#pragma unroll
    for (int jj = 0; jj < 7; jj++) {
        int p = e * 7 + jj;
        s += att[p] * __half2float(ctx[(size_t)p * HCTX + c]);
    }
    E[(size_t)e * HCTX + c] = __float2half(s);
}

__global__ void __launch_bounds__(256)
pack_k(const __half* __restrict__ S1, const __half* __restrict__ E,
       const __half* __restrict__ X, __half* __restrict__ T)
{
    int e = blockIdx.x;
    int t = threadIdx.x;
    T[(size_t)e * HTOT + t]       = S1[(size_t)e * HENC + t];
    T[(size_t)e * HTOT + 256 + t] = E[(size_t)e * HCTX + t];
    T[(size_t)e * HTOT + 512 + t] = X[(size_t)e * HIN + t];
    T[(size_t)e * HTOT + 768 + t] = X[(size_t)e * HIN + 256 + t];
}

extern "C" void kernel_launch(void* const* d_in, const int* in_sizes, int n_in,
                              void* d_out, int out_size)
{
    const float* inputs = (const float*)d_in[0];
    const float* state  = (const float*)d_in[1];
    const float* W_in   = (const float*)d_in[2];
    const float* b_in   = (const float*)d_in[3];
    const float* W_enc  = (const float*)d_in[4];
    const float* b_enc  = (const float*)d_in[5];
    const float* W_core = (const float*)d_in[6];
    const float* b_core = (const float*)d_in[7];
    const float* W_ctx  = (const float*)d_in[8];
    const float* b_ctx  = (const float*)d_in[9];
    const float* W_att  = (const float*)d_in[10];
    const float* b_att  = (const float*)d_in[11];
    const float* W_rec  = (const float*)d_in[12];
    const float* b_rec  = (const float*)d_in[13];
    const float* W_out  = (const float*)d_in[14];
    const float* b_out  = (const float*)d_in[15];

    float* out       = (float*)d_out;
    float* new_state = (float*)d_out + (size_t)BENT * MDIM;

    __half *pInh, *pSth, *pWinh, *pWench, *pWcoreh, *pWctxh, *pWrech, *pWouth;
    __half *pXh, *pS1h, *pCoreh, *pCtxh, *pEh, *pTh, *pNSh;
    float  *pAtt;
    cudaGetSymbolAddress((void**)&pInh,    g_inh);
    cudaGetSymbolAddress((void**)&pSth,    g_sth);
    cudaGetSymbolAddress((void**)&pWinh,   g_Winh);
    cudaGetSymbolAddress((void**)&pWench,  g_Wench);
    cudaGetSymbolAddress((void**)&pWcoreh, g_Wcoreh);
    cudaGetSymbolAddress((void**)&pWctxh,  g_Wctxh);
    cudaGetSymbolAddress((void**)&pWrech,  g_Wrech);
    cudaGetSymbolAddress((void**)&pWouth,  g_Wouth);
    cudaGetSymbolAddress((void**)&pXh,     g_Xh);
    cudaGetSymbolAddress((void**)&pS1h,    g_S1h);
    cudaGetSymbolAddress((void**)&pCoreh,  g_coreh);
    cudaGetSymbolAddress((void**)&pCtxh,   g_ctxh);
    cudaGetSymbolAddress((void**)&pAtt,    g_att);
    cudaGetSymbolAddress((void**)&pEh,     g_Eh);
    cudaGetSymbolAddress((void**)&pTh,     g_Th);
    cudaGetSymbolAddress((void**)&pNSh,    g_NSh);

    cudaFuncSetAttribute(hgemm<3,0,0>, cudaFuncAttributeMaxDynamicSharedMemorySize, SMEM_TOT);
    cudaFuncSetAttribute(hgemm<1,0,0>, cudaFuncAttributeMaxDynamicSharedMemorySize, SMEM_TOT);
    cudaFuncSetAttribute(hgemm<1,1,0>, cudaFuncAttributeMaxDynamicSharedMemorySize, SMEM_TOT);
    cudaFuncSetAttribute(hgemm<2,0,2>, cudaFuncAttributeMaxDynamicSharedMemorySize, SMEM_TOT);
    cudaFuncSetAttribute(hgemm<2,0,1>, cudaFuncAttributeMaxDynamicSharedMemorySize, SMEM_TOT);

    // 0) fp32 -> fp16 conversions
    cvt_k<<<(BENT*MDIM/8 + 255)/256, 256>>>(inputs, pInh, BENT*MDIM);
    cvt_k<<<(BENT*HSTATE/8 + 255)/256, 256>>>(state, pSth, BENT*HSTATE);
    cvt_k<<<(MDIM*HIN/8 + 255)/256, 256>>>(W_in, pWinh, MDIM*HIN);
    cvt_k<<<(HSTATE*HENC/8 + 255)/256, 256>>>(W_enc, pWench, HSTATE*HENC);
    cvt_k<<<(2*HENC*HCORE/8 + 255)/256, 256>>>(W_core, pWcoreh, 2*HENC*HCORE);
    cvt_k<<<(HCORE*HCTX/8 + 255)/256, 256>>>(W_ctx, pWctxh, HCORE*HCTX);
    cvt_k<<<(HTOT*HSTATE/8 + 255)/256, 256>>>(W_rec, pWrech, HTOT*HSTATE);
    cvt_k<<<(HSTATE*MDIM/8 + 255)/256, 256>>>(W_out, pWouth, HSTATE*MDIM);

    // 1) X = elu(inputs @ W_in)            [4096,512]  K=4096
    hgemm<3,0,0><<<dim3(HIN/128, BENT/128), 256, SMEM_TOT>>>(pInh, pWinh, b_in, pXh, nullptr, HIN, MDIM);
    // 2) S1 = relu(state @ W_enc)          [4096,256]  K=512
    hgemm<1,0,0><<<dim3(HENC/128, BENT/128), 256, SMEM_TOT>>>(pSth, pWench, b_enc, pS1h, nullptr, HENC, HSTATE);
    // 3) core = relu([cs|fs] @ W_core)     [28672,512] K=512 gathered
    hgemm<1,1,0><<<dim3(HCORE/128, NPAIR/128), 256, SMEM_TOT>>>(pS1h, pWcoreh, b_core, pCoreh, nullptr, HCORE, 2*HENC);
    // 4) ctx = relu(core @ W_ctx)          [28672,256] K=512
    hgemm<1,0,0><<<dim3(HCTX/128, NPAIR/128), 256, SMEM_TOT>>>(pCoreh, pWctxh, b_ctx, pCtxh, nullptr, HCTX, HCORE);
    // 5) att = sigmoid(core @ W_att)       [28672]
    att_k<<<(NPAIR * 32 + 255) / 256, 256>>>(pCoreh, W_att, b_att, pAtt);
    // 6) E = sum_j att*ctx                 [4096,256]
    esum_k<<<BENT, 256>>>(pCtxh, pAtt, pEh);
    // 7) T = [S1 | E | X]                  [4096,1024]
    pack_k<<<BENT, 256>>>(pS1h, pEh, pXh, pTh);
    // 8) new_state = sigmoid(T @ W_rec)    [4096,512]  K=1024 (fp32 out + fp16 copy)
    hgemm<2,0,2><<<dim3(HSTATE/128, BENT/128), 256, SMEM_TOT>>>(pTh, pWrech, b_rec, pNSh, new_state, HSTATE, HTOT);
    // 9) out = sigmoid(new_state @ W_out)  [4096,4096] K=512 (fp32 only)
    hgemm<2,0,1><<<dim3(MDIM/128, BENT/128), 256, SMEM_TOT>>>(pNSh, pWouth, b_out, nullptr, out, MDIM, HSTATE);
}